// round 12
// baseline (speedup 1.0000x reference)
#include <cuda_runtime.h>
#include <math.h>

#define NN   6000
#define EE   192000
#define DIN  512
#define HH   128
#define NPB  16          // nodes per block in p-kernel
#define EOSF 1e-10f

// Scratch (__device__ globals allowed; heap allocs are not).
__device__ int   g_win[(size_t)NN * NN];   // winner edge-index+1 per cell (only edge cells touched)
__device__ float g_p[NN];
__device__ float g_dlp[NN];
__device__ float g_dhp[NN];
__device__ float g_ilp[NN];
__device__ float g_ihp[NN];
__device__ float g_diag_lp[NN];
__device__ int   g_diag_skip[NN];          // 1 = self-edge winner covers the diagonal
// CSR over all edges, grouped by source row u.
__device__ int   g_cnt[NN];
__device__ int   g_pos[NN];
__device__ int   g_rowstart[NN + 1];
__device__ int   g_csr_v[EE];              // destination column per slot
__device__ int   g_slot[EE];               // edge -> slot
__device__ float g_csr_vlp[EE];            // per-slot adj_lp value (0 = not winner)
__device__ float g_csr_vhp[EE];

// ---- CSR build -------------------------------------------------------------
__global__ void k_cnt0() {
    int t = blockIdx.x * blockDim.x + threadIdx.x;
    if (t < NN) g_cnt[t] = 0;
}
__global__ void k_count(const int* __restrict__ edges) {
    int e = blockIdx.x * blockDim.x + threadIdx.x;
    if (e < EE) atomicAdd(&g_cnt[edges[e]], 1);
}
// Single-block exclusive scan over g_cnt -> g_rowstart / g_pos.
__global__ void __launch_bounds__(1024) k_scan() {
    __shared__ int part[1024];
    const int PER = (NN + 1023) / 1024;    // 6
    int tid = threadIdx.x;
    int base = tid * PER;
    int local[PER];
    int s = 0;
#pragma unroll
    for (int j = 0; j < PER; j++) {
        int idx = base + j;
        int c = (idx < NN) ? g_cnt[idx] : 0;
        local[j] = s;
        s += c;
    }
    part[tid] = s;
    __syncthreads();
    for (int off = 1; off < 1024; off <<= 1) {
        int v = (tid >= off) ? part[tid - off] : 0;
        __syncthreads();
        part[tid] += v;
        __syncthreads();
    }
    int prev = (tid == 0) ? 0 : part[tid - 1];
#pragma unroll
    for (int j = 0; j < PER; j++) {
        int idx = base + j;
        if (idx < NN) {
            int rs = prev + local[j];
            g_rowstart[idx] = rs;
            g_pos[idx] = rs;
        }
    }
    if (tid == 1023) g_rowstart[NN] = part[1023];
}
__global__ void k_fillcsr(const int* __restrict__ edges) {
    int e = blockIdx.x * blockDim.x + threadIdx.x;
    if (e >= EE) return;
    int u = edges[e], v = edges[EE + e];
    int slot = atomicAdd(&g_pos[u], 1);
    g_csr_v[slot] = v;
    g_slot[e] = slot;
}

// ---- winner bookkeeping ----------------------------------------------------
__global__ void k_clear(const int* __restrict__ edges) {
    int t = blockIdx.x * blockDim.x + threadIdx.x;
    if (t < EE) {
        int u = edges[t], v = edges[EE + t];
        g_win[u * NN + v] = 0;
    }
    if (t < NN) { g_dlp[t] = 1.0f; g_dhp[t] = 1.0f; }
}
__global__ void k_max(const int* __restrict__ edges) {
    int e = blockIdx.x * blockDim.x + threadIdx.x;
    if (e >= EE) return;
    int u = edges[e], v = edges[EE + e];
    atomicMax(&g_win[u * NN + v], e + 1);
}

// ---- node projection p[n] --------------------------------------------------
__global__ void __launch_bounds__(HH) k_p(const float* __restrict__ feat,
                                          const float* __restrict__ wemb,
                                          const float* __restrict__ bemb,
                                          const float* __restrict__ wmlp) {
    __shared__ float sf[NPB][DIN];
    int h  = threadIdx.x;
    int n0 = blockIdx.x * NPB;

    const float4* f4 = (const float4*)(feat + (size_t)n0 * DIN);
    float4* s4 = (float4*)&sf[0][0];
    const int total4 = NPB * DIN / 4;
    for (int i = h; i < total4; i += HH) s4[i] = f4[i];
    __syncthreads();

    float acc[NPB];
#pragma unroll
    for (int j = 0; j < NPB; j++) acc[j] = 0.0f;

    for (int d = 0; d < DIN; d += 4) {
        float w0 = wemb[(d + 0) * HH + h];
        float w1 = wemb[(d + 1) * HH + h];
        float w2 = wemb[(d + 2) * HH + h];
        float w3 = wemb[(d + 3) * HH + h];
#pragma unroll
        for (int j = 0; j < NPB; j++) {
            float4 f = *(const float4*)&sf[j][d];
            acc[j] = fmaf(f.x, w0, acc[j]);
            acc[j] = fmaf(f.y, w1, acc[j]);
            acc[j] = fmaf(f.z, w2, acc[j]);
            acc[j] = fmaf(f.w, w3, acc[j]);
        }
    }

    float b  = bemb[h];
    float ws = wmlp[h] + wmlp[HH + h];
    __shared__ float red[4][NPB];
#pragma unroll
    for (int j = 0; j < NPB; j++) {
        float v = acc[j] + b;
        v = (v > 0.0f) ? v * ws : 0.0f;
#pragma unroll
        for (int off = 16; off; off >>= 1) v += __shfl_down_sync(0xffffffffu, v, off);
        if ((h & 31) == 0) red[h >> 5][j] = v;
    }
    __syncthreads();
    if (h < NPB)
        g_p[n0 + h] = red[0][h] + red[1][h] + red[2][h] + red[3][h];
}

// ---- gating + degrees ------------------------------------------------------
__global__ void k_edge(const int* __restrict__ edges, const float* __restrict__ gn,
                       const float* __restrict__ bmlp,
                       float* __restrict__ wlp_out, float* __restrict__ whp_out) {
    int e = blockIdx.x * blockDim.x + threadIdx.x;
    if (e >= EE) return;
    int u = edges[e], v = edges[EE + e];
    float raw = 0.5f * (g_p[u] + g_p[v]) + bmlp[0];
    float x   = gn[e] + raw;               // TEMP = 1
    float wlp = 1.0f / (1.0f + expf(-x));
    wlp_out[e] = wlp;
    whp_out[e] = 1.0f - wlp;
    if (g_win[u * NN + v] == e + 1) {
        atomicAdd(&g_dlp[u], wlp);
        atomicAdd(&g_dhp[u], 1.0f - wlp);
    }
}

__global__ void k_inv() {
    int i = blockIdx.x * blockDim.x + threadIdx.x;
    if (i >= NN) return;
    float il = 1.0f / (sqrtf(g_dlp[i]) + EOSF);
    float ih = 1.0f / (sqrtf(g_dhp[i]) + EOSF);
    g_ilp[i] = il;
    g_ihp[i] = ih;
    g_diag_skip[i] = (g_win[(size_t)i * NN + i] != 0);
    g_diag_lp[i] = il * il;
}

// Per-edge values written slot-ordered for coalesced row composition.
__global__ void k_vals(const int* __restrict__ edges, const float* __restrict__ wlp_out) {
    int e = blockIdx.x * blockDim.x + threadIdx.x;
    if (e >= EE) return;
    int u = edges[e], v = edges[EE + e];
    size_t cell = (size_t)u * NN + v;
    float vlp = 0.0f, vhp = 0.0f;
    if (g_win[cell] == e + 1) {
        float wlp = wlp_out[e];
        float il = g_ilp[u] * g_ilp[v];
        float ih = g_ihp[u] * g_ihp[v];
        if (u == v) {
            vlp = (1.0f + wlp) * il;             // eye + self-edge, normalized
            vhp = 1.0f - (2.0f - wlp) * ih;      // 1 - (whp + 1)*ih
        } else {
            vlp = wlp * il;
            vhp = -(1.0f - wlp) * ih;
        }
    }
    int slot = g_slot[e];
    g_csr_vlp[slot] = vlp;
    g_csr_vhp[slot] = vhp;
}

// ---- fused row writers: compose each row in SMEM, stream out once ----------
__global__ void __launch_bounds__(256) k_wrow_unnorm(float* __restrict__ unnorm) {
    __shared__ float row[NN];                 // 24000 B
    int r = blockIdx.x;
    float4* r4 = (float4*)row;
    const float4 z = make_float4(0.f, 0.f, 0.f, 0.f);
    for (int i = threadIdx.x; i < NN / 4; i += 256) r4[i] = z;
    __syncthreads();
    int s0 = g_rowstart[r], s1 = g_rowstart[r + 1];
    for (int s = s0 + threadIdx.x; s < s1; s += 256) row[g_csr_v[s]] = 1.0f;
    __syncthreads();
    float4* dst = (float4*)(unnorm + (size_t)r * NN);
    for (int i = threadIdx.x; i < NN / 4; i += 256) __stwt(dst + i, r4[i]);
}

__global__ void __launch_bounds__(256) k_wrow_adj(float* __restrict__ adj_lp,
                                                  float* __restrict__ adj_hp) {
    __shared__ float slp[NN];                 // 24000 B
    __shared__ float shp[NN];                 // 24000 B
    int r = blockIdx.x;
    float4* l4 = (float4*)slp;
    float4* h4 = (float4*)shp;
    const float4 z = make_float4(0.f, 0.f, 0.f, 0.f);
    for (int i = threadIdx.x; i < NN / 4; i += 256) { l4[i] = z; h4[i] = z; }
    __syncthreads();
    int s0 = g_rowstart[r], s1 = g_rowstart[r + 1];
    for (int s = s0 + threadIdx.x; s < s1; s += 256) {
        float vlp = g_csr_vlp[s];
        if (vlp != 0.0f) {                    // winner edges only
            int v = g_csr_v[s];
            slp[v] = vlp;
            shp[v] = g_csr_vhp[s];
        }
    }
    if (threadIdx.x == 0 && !g_diag_skip[r]) {
        slp[r] = g_diag_lp[r];
        shp[r] = 1.0f;
    }
    __syncthreads();
    float4* dl = (float4*)(adj_lp + (size_t)r * NN);
    float4* dh = (float4*)(adj_hp + (size_t)r * NN);
    for (int i = threadIdx.x; i < NN / 4; i += 256) {
        __stwt(dl + i, l4[i]);
        __stwt(dh + i, h4[i]);
    }
}

extern "C" void kernel_launch(void* const* d_in, const int* in_sizes, int n_in,
                              void* d_out, int out_size) {
    const float* feat  = (const float*)d_in[0];
    const int*   edges = (const int*)  d_in[1];
    const float* wemb  = (const float*)d_in[2];
    const float* bemb  = (const float*)d_in[3];
    const float* wmlp  = (const float*)d_in[4];
    const float* bmlp  = (const float*)d_in[5];
    const float* gn    = (const float*)d_in[6];

    float* out     = (float*)d_out;
    float* adj_lp  = out;
    float* adj_hp  = out + (size_t)NN * NN;
    float* wlp     = out + 2ull * NN * NN;
    float* whp     = wlp + EE;
    float* unnorm  = whp + EE;

    static cudaStream_t s_f = nullptr, s_p = nullptr;
    static cudaEvent_t ev_fork = nullptr, ev_p = nullptr, ev_csr = nullptr,
                       ev_unw = nullptr;
    if (!s_f) {
        cudaStreamCreateWithFlags(&s_f, cudaStreamNonBlocking);
        cudaStreamCreateWithFlags(&s_p, cudaStreamNonBlocking);
        cudaEventCreateWithFlags(&ev_fork, cudaEventDisableTiming);
        cudaEventCreateWithFlags(&ev_p,    cudaEventDisableTiming);
        cudaEventCreateWithFlags(&ev_csr,  cudaEventDisableTiming);
        cudaEventCreateWithFlags(&ev_unw,  cudaEventDisableTiming);
    }

    const int TB = 256;

    // Fork.
    cudaEventRecord(ev_fork, 0);
    cudaStreamWaitEvent(s_f, ev_fork, 0);
    cudaStreamWaitEvent(s_p, ev_fork, 0);

    // Writer stream: CSR build, then the unnorm fused row-write (144 MB, only
    // needs edge positions).
    k_cnt0   <<<(NN + TB - 1) / TB, TB, 0, s_f>>>();
    k_count  <<<(EE + TB - 1) / TB, TB, 0, s_f>>>(edges);
    k_scan   <<<1, 1024, 0, s_f>>>();
    k_fillcsr<<<(EE + TB - 1) / TB, TB, 0, s_f>>>(edges);
    cudaEventRecord(ev_csr, s_f);
    k_wrow_unnorm<<<NN, 256, 0, s_f>>>(unnorm);
    cudaEventRecord(ev_unw, s_f);

    // p stream: node scalar projection (NPB=16 -> half the w_emb L2 traffic).
    k_p<<<NN / NPB, HH, 0, s_p>>>(feat, wemb, bemb, wmlp);
    cudaEventRecord(ev_p, s_p);

    // Main chain: winner bookkeeping, gating, norms, slot-ordered values.
    k_clear<<<(EE + TB - 1) / TB, TB>>>(edges);
    k_max  <<<(EE + TB - 1) / TB, TB>>>(edges);
    cudaStreamWaitEvent(0, ev_p, 0);
    k_edge <<<(EE + TB - 1) / TB, TB>>>(edges, gn, bmlp, wlp, whp);
    k_inv  <<<(NN + TB - 1) / TB, TB>>>();
    cudaStreamWaitEvent(0, ev_csr, 0);
    k_vals <<<(EE + TB - 1) / TB, TB>>>(edges, wlp);

    // Adjacency fused row-write (288 MB) — values ready, unnorm write drained.
    cudaStreamWaitEvent(0, ev_unw, 0);
    k_wrow_adj<<<NN, 256>>>(adj_lp, adj_hp);
}